// round 1
// baseline (speedup 1.0000x reference)
#include <cuda_runtime.h>
#include <math.h>

// Problem constants
#define NB    4        // batch
#define SS    128      // spatial H = W
#define CDIM  256      // model dim
#define NHH   4        // heads per branch
#define DHH   32       // head dim
#define NWIN  256      // 16x16 windows
#define WSZ   64       // 8x8 tokens per window
#define MTOT  (NB*SS*SS)   // 65536 rows
#define QSCALE 0.17677669529663687f  // 32^-0.5

// Scratch (static device memory; no allocations allowed)
__device__ float g_q   [MTOT * CDIM];        // 64 MB
__device__ float g_kv  [MTOT * 2 * CDIM];    // 128 MB: [k(256) | v(256)]
__device__ float g_att [MTOT * CDIM];        // 64 MB, windowed layout [b][n][m][c]
__device__ float g_pos1t[NHH * WSZ * WSZ];   // pos1 transposed: [h][j][i]
__device__ float g_pos2t[NHH * NWIN * NWIN]; // pos2 transposed: [h][j][i]

// ---------------------------------------------------------------------------
// Transpose positional biases so per-key reads are coalesced across queries
// ---------------------------------------------------------------------------
__global__ void pos_transpose(const float* __restrict__ p1,
                              const float* __restrict__ p2) {
    int idx = blockIdx.x * blockDim.x + threadIdx.x;
    int stride = gridDim.x * blockDim.x;
    for (int i = idx; i < NHH * WSZ * WSZ; i += stride) {
        int hh = i / (WSZ * WSZ);
        int rem = i - hh * WSZ * WSZ;
        int r = rem / WSZ, c = rem % WSZ;
        g_pos1t[(hh * WSZ + c) * WSZ + r] = p1[i];
    }
    for (int i = idx; i < NHH * NWIN * NWIN; i += stride) {
        int hh = i / (NWIN * NWIN);
        int rem = i - hh * NWIN * NWIN;
        int r = rem / NWIN, c = rem % NWIN;
        g_pos2t[(hh * NWIN + c) * NWIN + r] = p2[i];
    }
}

// ---------------------------------------------------------------------------
// Fused QKV projection: [q | kv] = x @ [Wq | Wkv]
// M=65536, K=256, N=768 (cols 0..255 -> g_q, 256..767 -> g_kv)
// Classic 128x128x8 SGEMM, 256 threads, 8x8 per thread.
// ---------------------------------------------------------------------------
__global__ __launch_bounds__(256) void gemm_qkv(
    const float* __restrict__ X,
    const float* __restrict__ Wq,
    const float* __restrict__ Wkv)
{
    const int BK = 8;
    __shared__ float As[BK][128];
    __shared__ float Bs[BK][128];
    int tid = threadIdx.x;
    int bcol = blockIdx.x;      // 0..5
    int brow = blockIdx.y;      // 0..511

    const float* Bb; int ldb;
    float* Cb; int ldc;
    if (bcol < 2) { Bb = Wq  + bcol * 128;        ldb = 256; Cb = g_q  + bcol * 128;        ldc = 256; }
    else          { Bb = Wkv + bcol * 128 - 256;  ldb = 512; Cb = g_kv + bcol * 128 - 256;  ldc = 512; }

    const float* Ab = X + (size_t)brow * 128 * 256;

    int aRow = tid >> 1, aCol = (tid & 1) * 4;
    int bRow = tid >> 5, bCol = (tid & 31) * 4;
    int ty = (tid >> 4) * 8, tx = (tid & 15) * 8;

    float acc[8][8] = {};

    for (int k0 = 0; k0 < 256; k0 += BK) {
        float4 a4 = *(const float4*)(Ab + aRow * 256 + k0 + aCol);
        As[aCol + 0][aRow] = a4.x;
        As[aCol + 1][aRow] = a4.y;
        As[aCol + 2][aRow] = a4.z;
        As[aCol + 3][aRow] = a4.w;
        *(float4*)(&Bs[bRow][bCol]) = *(const float4*)(Bb + (k0 + bRow) * ldb + bCol);
        __syncthreads();
#pragma unroll
        for (int kk = 0; kk < BK; kk++) {
            float ra[8], rb[8];
            *(float4*)(ra)     = *(const float4*)(&As[kk][ty]);
            *(float4*)(ra + 4) = *(const float4*)(&As[kk][ty + 4]);
            *(float4*)(rb)     = *(const float4*)(&Bs[kk][tx]);
            *(float4*)(rb + 4) = *(const float4*)(&Bs[kk][tx + 4]);
#pragma unroll
            for (int i = 0; i < 8; i++)
#pragma unroll
                for (int j = 0; j < 8; j++)
                    acc[i][j] += ra[i] * rb[j];
        }
        __syncthreads();
    }
#pragma unroll
    for (int i = 0; i < 8; i++) {
        size_t row = (size_t)brow * 128 + ty + i;
        float* Cr = Cb + row * ldc + tx;
#pragma unroll
        for (int j = 0; j < 8; j += 4) {
            *(float4*)(Cr + j) = make_float4(acc[i][j], acc[i][j+1], acc[i][j+2], acc[i][j+3]);
        }
    }
}

// ---------------------------------------------------------------------------
// Output projection: out = unwindow( g_att @ Wo + bo )
// ---------------------------------------------------------------------------
__device__ __forceinline__ int remap_row(int row) {
    // row = ((b*256 + n)*64 + m)  ->  b*16384 + h*128 + w
    int b = row >> 14;
    int n = (row >> 6) & 255;
    int m = row & 63;
    int h = ((n >> 4) << 3) + (m >> 3);
    int w = ((n & 15) << 3) + (m & 7);
    return (b << 14) + (h << 7) + w;
}

__global__ __launch_bounds__(256) void gemm_out(
    const float* __restrict__ Wo,
    const float* __restrict__ bo,
    float* __restrict__ out)
{
    const int BK = 8;
    __shared__ float As[BK][128];
    __shared__ float Bs[BK][128];
    int tid = threadIdx.x;
    int bcol = blockIdx.x;   // 0..1
    int brow = blockIdx.y;   // 0..511

    const float* Ab = g_att + (size_t)brow * 128 * 256;
    const float* Bb = Wo + bcol * 128;

    int aRow = tid >> 1, aCol = (tid & 1) * 4;
    int bRow = tid >> 5, bCol = (tid & 31) * 4;
    int ty = (tid >> 4) * 8, tx = (tid & 15) * 8;

    float acc[8][8] = {};

    for (int k0 = 0; k0 < 256; k0 += BK) {
        float4 a4 = *(const float4*)(Ab + aRow * 256 + k0 + aCol);
        As[aCol + 0][aRow] = a4.x;
        As[aCol + 1][aRow] = a4.y;
        As[aCol + 2][aRow] = a4.z;
        As[aCol + 3][aRow] = a4.w;
        *(float4*)(&Bs[bRow][bCol]) = *(const float4*)(Bb + (k0 + bRow) * 256 + bCol);
        __syncthreads();
#pragma unroll
        for (int kk = 0; kk < BK; kk++) {
            float ra[8], rb[8];
            *(float4*)(ra)     = *(const float4*)(&As[kk][ty]);
            *(float4*)(ra + 4) = *(const float4*)(&As[kk][ty + 4]);
            *(float4*)(rb)     = *(const float4*)(&Bs[kk][tx]);
            *(float4*)(rb + 4) = *(const float4*)(&Bs[kk][tx + 4]);
#pragma unroll
            for (int i = 0; i < 8; i++)
#pragma unroll
                for (int j = 0; j < 8; j++)
                    acc[i][j] += ra[i] * rb[j];
        }
        __syncthreads();
    }
#pragma unroll
    for (int i = 0; i < 8; i++) {
        int row = brow * 128 + ty + i;
        size_t orow = (size_t)remap_row(row);
        float* Cr = out + orow * 256 + bcol * 128 + tx;
#pragma unroll
        for (int j = 0; j < 8; j += 4) {
            int col = bcol * 128 + tx + j;
            float4 v = make_float4(acc[i][j]   + bo[col],
                                   acc[i][j+1] + bo[col+1],
                                   acc[i][j+2] + bo[col+2],
                                   acc[i][j+3] + bo[col+3]);
            *(float4*)(Cr + j) = v;
        }
    }
}

// ---------------------------------------------------------------------------
// Branch 1 attention: within each 8x8 window, seq=64, channels 0..127
// grid (n=256, hh=4, b=4), block 64 threads (one query row each)
// ---------------------------------------------------------------------------
__global__ __launch_bounds__(64) void attn1_kernel() {
    int n  = blockIdx.x;
    int hh = blockIdx.y;
    int b  = blockIdx.z;
    int i  = threadIdx.x;   // query position within window, 0..63

    __shared__ float ks[WSZ][36];
    __shared__ float vs[WSZ][36];

    // Spatial row for (b, window n, position i)
    int h = ((n >> 4) << 3) + (i >> 3);
    int w = ((n & 15) << 3) + (i & 7);
    size_t grow = ((size_t)b << 14) + (h << 7) + w;

    // Fill K/V rows (thread i owns key row i). k1: kv cols hh*32; v1: 256+hh*32
    {
        const float4* kp = (const float4*)(g_kv + grow * 512 + hh * DHH);
        const float4* vp = (const float4*)(g_kv + grow * 512 + 256 + hh * DHH);
#pragma unroll
        for (int d4 = 0; d4 < 8; d4++) {
            *(float4*)(&ks[i][d4 * 4]) = kp[d4];
            *(float4*)(&vs[i][d4 * 4]) = vp[d4];
        }
    }
    // Load q row (channels hh*32 .. +32), pre-scaled
    float qr[DHH];
    {
        const float4* qp = (const float4*)(g_q + grow * 256 + hh * DHH);
#pragma unroll
        for (int d4 = 0; d4 < 8; d4++) {
            float4 q4 = qp[d4];
            qr[d4*4+0] = q4.x * QSCALE; qr[d4*4+1] = q4.y * QSCALE;
            qr[d4*4+2] = q4.z * QSCALE; qr[d4*4+3] = q4.w * QSCALE;
        }
    }
    __syncthreads();

    const float* pos = g_pos1t + hh * WSZ * WSZ;  // [j][i]
    float mrun = -INFINITY, l = 0.f;
    float acc[DHH] = {};

    for (int j = 0; j < WSZ; j++) {
        float s = 0.f;
#pragma unroll
        for (int d4 = 0; d4 < 8; d4++) {
            float4 kk = *(const float4*)(&ks[j][d4 * 4]);
            s += qr[d4*4+0]*kk.x + qr[d4*4+1]*kk.y + qr[d4*4+2]*kk.z + qr[d4*4+3]*kk.w;
        }
        s += pos[j * WSZ + i];
        if (s > mrun) {
            float c = __expf(mrun - s);
            mrun = s; l *= c;
#pragma unroll
            for (int d = 0; d < DHH; d++) acc[d] *= c;
        }
        float p = __expf(s - mrun);
        l += p;
#pragma unroll
        for (int d4 = 0; d4 < 8; d4++) {
            float4 vv = *(const float4*)(&vs[j][d4 * 4]);
            acc[d4*4+0] += p * vv.x; acc[d4*4+1] += p * vv.y;
            acc[d4*4+2] += p * vv.z; acc[d4*4+3] += p * vv.w;
        }
    }
    float inv = 1.f / l;
    float* op = g_att + (((size_t)(b * NWIN + n) * WSZ) + i) * CDIM + hh * DHH;
#pragma unroll
    for (int d = 0; d < DHH; d += 4)
        *(float4*)(op + d) = make_float4(acc[d]*inv, acc[d+1]*inv, acc[d+2]*inv, acc[d+3]*inv);
}

// ---------------------------------------------------------------------------
// Branch 2 attention: across 256 windows at fixed within-window pos m,
// channels 128..255.  grid (m=64, hh=4, b=4), block 256 threads.
// K/V streamed in two 128-row chunks (36 KB smem).
// ---------------------------------------------------------------------------
__global__ __launch_bounds__(256) void attn2_kernel() {
    int m  = blockIdx.x;    // within-window position 0..63
    int hh = blockIdx.y;
    int b  = blockIdx.z;
    int i  = threadIdx.x;   // query window index 0..255

    __shared__ float ks[128][36];
    __shared__ float vs[128][36];

    // q row: window i, position m; channels 128 + hh*32
    int h = ((i >> 4) << 3) + (m >> 3);
    int w = ((i & 15) << 3) + (m & 7);
    size_t grow = ((size_t)b << 14) + (h << 7) + w;

    float qr[DHH];
    {
        const float4* qp = (const float4*)(g_q + grow * 256 + 128 + hh * DHH);
#pragma unroll
        for (int d4 = 0; d4 < 8; d4++) {
            float4 q4 = qp[d4];
            qr[d4*4+0] = q4.x * QSCALE; qr[d4*4+1] = q4.y * QSCALE;
            qr[d4*4+2] = q4.z * QSCALE; qr[d4*4+3] = q4.w * QSCALE;
        }
    }

    const float* pos = g_pos2t + hh * NWIN * NWIN;  // [j][i]
    float mrun = -INFINITY, l = 0.f;
    float acc[DHH] = {};

    for (int jc = 0; jc < NWIN; jc += 128) {
        __syncthreads();
        // 256 threads fill 128 K rows + 128 V rows
        {
            int t = threadIdx.x;
            int r = t & 127;
            int jw = jc + r;
            int hK = ((jw >> 4) << 3) + (m >> 3);
            int wK = ((jw & 15) << 3) + (m & 7);
            size_t gk = ((size_t)b << 14) + (hK << 7) + wK;
            if (t < 128) {
                const float4* kp = (const float4*)(g_kv + gk * 512 + 128 + hh * DHH);
#pragma unroll
                for (int d4 = 0; d4 < 8; d4++) *(float4*)(&ks[r][d4 * 4]) = kp[d4];
            } else {
                const float4* vp = (const float4*)(g_kv + gk * 512 + 384 + hh * DHH);
#pragma unroll
                for (int d4 = 0; d4 < 8; d4++) *(float4*)(&vs[r][d4 * 4]) = vp[d4];
            }
        }
        __syncthreads();

        for (int jj = 0; jj < 128; jj++) {
            int j = jc + jj;
            float s = 0.f;
#pragma unroll
            for (int d4 = 0; d4 < 8; d4++) {
                float4 kk = *(const float4*)(&ks[jj][d4 * 4]);
                s += qr[d4*4+0]*kk.x + qr[d4*4+1]*kk.y + qr[d4*4+2]*kk.z + qr[d4*4+3]*kk.w;
            }
            s += pos[j * NWIN + i];
            if (s > mrun) {
                float c = __expf(mrun - s);
                mrun = s; l *= c;
#pragma unroll
                for (int d = 0; d < DHH; d++) acc[d] *= c;
            }
            float p = __expf(s - mrun);
            l += p;
#pragma unroll
            for (int d4 = 0; d4 < 8; d4++) {
                float4 vv = *(const float4*)(&vs[jj][d4 * 4]);
                acc[d4*4+0] += p * vv.x; acc[d4*4+1] += p * vv.y;
                acc[d4*4+2] += p * vv.z; acc[d4*4+3] += p * vv.w;
            }
        }
    }
    float inv = 1.f / l;
    // out2 (transposed back): att[b][n=i][m][128 + hh*32 + d]
    float* op = g_att + (((size_t)(b * NWIN + i) * WSZ) + m) * CDIM + 128 + hh * DHH;
#pragma unroll
    for (int d = 0; d < DHH; d += 4)
        *(float4*)(op + d) = make_float4(acc[d]*inv, acc[d+1]*inv, acc[d+2]*inv, acc[d+3]*inv);
}

// ---------------------------------------------------------------------------
extern "C" void kernel_launch(void* const* d_in, const int* in_sizes, int n_in,
                              void* d_out, int out_size) {
    const float* x   = (const float*)d_in[0];
    const float* Wq  = (const float*)d_in[1];
    const float* Wkv = (const float*)d_in[2];
    const float* Wo  = (const float*)d_in[3];
    const float* bo  = (const float*)d_in[4];
    const float* p1  = (const float*)d_in[5];
    const float* p2  = (const float*)d_in[6];
    float* out = (float*)d_out;

    pos_transpose<<<256, 256>>>(p1, p2);
    gemm_qkv<<<dim3(6, 512), 256>>>(x, Wq, Wkv);
    attn1_kernel<<<dim3(256, 4, 4), 64>>>();
    attn2_kernel<<<dim3(64, 4, 4), 256>>>();
    gemm_out<<<dim3(2, 512), 256>>>(Wo, bo, out);
}

// round 4
// speedup vs baseline: 1.3570x; 1.3570x over previous
#include <cuda_runtime.h>
#include <cuda_bf16.h>
#include <mma.h>
#include <math.h>

using namespace nvcuda;

#define NB    4
#define SS    128
#define CDIM  256
#define NHH   4
#define DHH   32
#define NWIN  256
#define WSZ   64
#define MTOT  (NB*SS*SS)
#define NQKV  768
#define QSCALE 0.17677669529663687f

// ---------------- scratch ----------------
__device__ float g_q  [MTOT * CDIM];
__device__ float g_kv [MTOT * 2 * CDIM];
__device__ __nv_bfloat16 g_xhi[MTOT * CDIM];
__device__ __nv_bfloat16 g_xlo[MTOT * CDIM];
__device__ __nv_bfloat16 g_ahi[MTOT * CDIM];
__device__ __nv_bfloat16 g_alo[MTOT * CDIM];
__device__ __nv_bfloat16 g_whi[CDIM * NQKV];
__device__ __nv_bfloat16 g_wlo[CDIM * NQKV];
__device__ __nv_bfloat16 g_wohi[CDIM * CDIM];
__device__ __nv_bfloat16 g_wolo[CDIM * CDIM];
__device__ float g_pos1t[NHH * WSZ * WSZ];
__device__ float g_pos2t[NHH * NWIN * NWIN];

__device__ __forceinline__ void split1(float x, __nv_bfloat16& h, __nv_bfloat16& l) {
    h = __float2bfloat16(x);
    l = __float2bfloat16(x - __bfloat162float(h));
}

// ---------------- pos transpose ----------------
__global__ void pos_transpose(const float* __restrict__ p1,
                              const float* __restrict__ p2) {
    int idx = blockIdx.x * blockDim.x + threadIdx.x;
    int stride = gridDim.x * blockDim.x;
    for (int i = idx; i < NHH * WSZ * WSZ; i += stride) {
        int hh = i / (WSZ * WSZ);
        int rem = i - hh * WSZ * WSZ;
        int r = rem / WSZ;
        int c = rem % WSZ;
        g_pos1t[(hh * WSZ + c) * WSZ + r] = p1[i];
    }
    for (int i = idx; i < NHH * NWIN * NWIN; i += stride) {
        int hh = i / (NWIN * NWIN);
        int rem = i - hh * NWIN * NWIN;
        int r = rem / NWIN;
        int c = rem % NWIN;
        g_pos2t[(hh * NWIN + c) * NWIN + r] = p2[i];
    }
}

// ---------------- conversions ----------------
__global__ void split_x(const float* __restrict__ src) {
    int idx = blockIdx.x * blockDim.x + threadIdx.x;
    int stride = gridDim.x * blockDim.x;
    const int n4 = MTOT * CDIM / 4;
    for (int i = idx; i < n4; i += stride) {
        float4 v = ((const float4*)src)[i];
        __nv_bfloat16 h4[4];
        __nv_bfloat16 l4[4];
        split1(v.x, h4[0], l4[0]);
        split1(v.y, h4[1], l4[1]);
        split1(v.z, h4[2], l4[2]);
        split1(v.w, h4[3], l4[3]);
        ((uint2*)g_xhi)[i] = *(uint2*)h4;
        ((uint2*)g_xlo)[i] = *(uint2*)l4;
    }
}

__global__ void split_wo(const float* __restrict__ Wo) {
    int i = blockIdx.x * blockDim.x + threadIdx.x;
    if (i < CDIM * CDIM) {
        split1(Wo[i], g_wohi[i], g_wolo[i]);
    }
}

__global__ void build_w(const float* __restrict__ Wq, const float* __restrict__ Wkv) {
    int idx = blockIdx.x * blockDim.x + threadIdx.x;
    if (idx < CDIM * NQKV) {
        int k = idx / NQKV;
        int c = idx % NQKV;
        float v = (c < 256) ? Wq[k * 256 + c] : Wkv[k * 512 + (c - 256)];
        split1(v, g_whi[idx], g_wlo[idx]);
    }
}

// ---------------- WMMA split-bf16 GEMM ----------------
__device__ __forceinline__ int remap_row(int row) {
    int b = row >> 14;
    int n = (row >> 6) & 255;
    int m = row & 63;
    int h = ((n >> 4) << 3) + (m >> 3);
    int w = ((n & 15) << 3) + (m & 7);
    return (b << 14) + (h << 7) + w;
}

__global__ __launch_bounds__(256) void gemm_wmma(
    int mode, float* __restrict__ outp, const float* __restrict__ bo)
{
    const int Ntot = mode ? 256 : NQKV;
    const __nv_bfloat16* __restrict__ Ahi = mode ? g_ahi : g_xhi;
    const __nv_bfloat16* __restrict__ Alo = mode ? g_alo : g_xlo;
    const __nv_bfloat16* __restrict__ Bhi = mode ? g_wohi : g_whi;
    const __nv_bfloat16* __restrict__ Blo = mode ? g_wolo : g_wlo;

    __shared__ __align__(32) __nv_bfloat16 As[2][128][40];
    __shared__ __align__(32) __nv_bfloat16 Bs[2][32][136];
    __shared__ __align__(32) float stg[8][16][16];

    const int tid = threadIdx.x;
    const int wid = tid >> 5;
    const int lane = tid & 31;
    const int nb0 = blockIdx.x * 128;
    const int mrow0 = blockIdx.y * 128;
    const int m0w = (wid & 3) * 32;
    const int n0w = (wid >> 2) * 64;

    wmma::fragment<wmma::accumulator, 16, 16, 16, float> cfrag[2][4];
#pragma unroll
    for (int mi = 0; mi < 2; mi++) {
#pragma unroll
        for (int ni = 0; ni < 4; ni++) {
            wmma::fill_fragment(cfrag[mi][ni], 0.0f);
        }
    }

    const int arow = tid >> 1;
    const int acol = (tid & 1) * 16;
    const int bkr = tid >> 4;
    const int bnc = (tid & 15) * 8;

    for (int k0 = 0; k0 < 256; k0 += 32) {
        __syncthreads();
        {
            const __nv_bfloat16* ah = Ahi + (size_t)(mrow0 + arow) * 256 + k0 + acol;
            const __nv_bfloat16* al = Alo + (size_t)(mrow0 + arow) * 256 + k0 + acol;
            *(uint4*)(&As[0][arow][acol])     = *(const uint4*)(ah);
            *(uint4*)(&As[0][arow][acol + 8]) = *(const uint4*)(ah + 8);
            *(uint4*)(&As[1][arow][acol])     = *(const uint4*)(al);
            *(uint4*)(&As[1][arow][acol + 8]) = *(const uint4*)(al + 8);
        }
#pragma unroll
        for (int p = 0; p < 32; p += 16) {
            *(uint4*)(&Bs[0][bkr + p][bnc]) =
                *(const uint4*)(Bhi + (size_t)(k0 + bkr + p) * Ntot + nb0 + bnc);
            *(uint4*)(&Bs[1][bkr + p][bnc]) =
                *(const uint4*)(Blo + (size_t)(k0 + bkr + p) * Ntot + nb0 + bnc);
        }
        __syncthreads();

#pragma unroll
        for (int ks = 0; ks < 32; ks += 16) {
            wmma::fragment<wmma::matrix_a, 16, 16, 16, __nv_bfloat16, wmma::row_major> afh[2];
            wmma::fragment<wmma::matrix_a, 16, 16, 16, __nv_bfloat16, wmma::row_major> afl[2];
            wmma::load_matrix_sync(afh[0], &As[0][m0w][ks], 40);
            wmma::load_matrix_sync(afh[1], &As[0][m0w + 16][ks], 40);
            wmma::load_matrix_sync(afl[0], &As[1][m0w][ks], 40);
            wmma::load_matrix_sync(afl[1], &As[1][m0w + 16][ks], 40);
#pragma unroll
            for (int ni = 0; ni < 4; ni++) {
                wmma::fragment<wmma::matrix_b, 16, 16, 16, __nv_bfloat16, wmma::row_major> bfh;
                wmma::fragment<wmma::matrix_b, 16, 16, 16, __nv_bfloat16, wmma::row_major> bfl;
                wmma::load_matrix_sync(bfh, &Bs[0][ks][n0w + ni * 16], 136);
                wmma::load_matrix_sync(bfl, &Bs[1][ks][n0w + ni * 16], 136);
#pragma unroll
                for (int mi = 0; mi < 2; mi++) {
                    wmma::mma_sync(cfrag[mi][ni], afh[mi], bfh, cfrag[mi][ni]);
                    wmma::mma_sync(cfrag[mi][ni], afh[mi], bfl, cfrag[mi][ni]);
                    wmma::mma_sync(cfrag[mi][ni], afl[mi], bfh, cfrag[mi][ni]);
                }
            }
        }
    }

    if (mode == 0) {
#pragma unroll
        for (int mi = 0; mi < 2; mi++) {
#pragma unroll
            for (int ni = 0; ni < 4; ni++) {
                int row = mrow0 + m0w + mi * 16;
                int col = nb0 + n0w + ni * 16;
                if (col < 256) {
                    wmma::store_matrix_sync(g_q + (size_t)row * 256 + col,
                                            cfrag[mi][ni], 256, wmma::mem_row_major);
                } else {
                    wmma::store_matrix_sync(g_kv + (size_t)row * 512 + (col - 256),
                                            cfrag[mi][ni], 512, wmma::mem_row_major);
                }
            }
        }
    } else {
#pragma unroll
        for (int mi = 0; mi < 2; mi++) {
#pragma unroll
            for (int ni = 0; ni < 4; ni++) {
                wmma::store_matrix_sync(&stg[wid][0][0], cfrag[mi][ni], 16, wmma::mem_row_major);
                __syncwarp();
                int row0 = mrow0 + m0w + mi * 16;
                int col0 = nb0 + n0w + ni * 16;
#pragma unroll
                for (int e = 0; e < 8; e++) {
                    int idx = lane * 8 + e;
                    int r = idx >> 4;
                    int c = idx & 15;
                    int grow = remap_row(row0 + r);
                    outp[(size_t)grow * 256 + col0 + c] = stg[wid][r][c] + bo[col0 + c];
                }
                __syncwarp();
            }
        }
    }
}

// ---------------- attention branch 1 (within-window, seq=64) ----------------
__global__ __launch_bounds__(64) void attn1_kernel() {
    int n  = blockIdx.x;
    int hh = blockIdx.y;
    int b  = blockIdx.z;
    int i  = threadIdx.x;

    __shared__ float ks[WSZ][36];
    __shared__ float vs[WSZ][36];

    int h = ((n >> 4) << 3) + (i >> 3);
    int w = ((n & 15) << 3) + (i & 7);
    size_t grow = ((size_t)b << 14) + (h << 7) + w;

    {
        const float4* kp = (const float4*)(g_kv + grow * 512 + hh * DHH);
        const float4* vp = (const float4*)(g_kv + grow * 512 + 256 + hh * DHH);
#pragma unroll
        for (int d4 = 0; d4 < 8; d4++) {
            *(float4*)(&ks[i][d4 * 4]) = kp[d4];
            *(float4*)(&vs[i][d4 * 4]) = vp[d4];
        }
    }
    float qr[DHH];
    {
        const float4* qp = (const float4*)(g_q + grow * 256 + hh * DHH);
#pragma unroll
        for (int d4 = 0; d4 < 8; d4++) {
            float4 q4 = qp[d4];
            qr[d4*4+0] = q4.x * QSCALE;
            qr[d4*4+1] = q4.y * QSCALE;
            qr[d4*4+2] = q4.z * QSCALE;
            qr[d4*4+3] = q4.w * QSCALE;
        }
    }
    __syncthreads();

    const float* pos = g_pos1t + hh * WSZ * WSZ;
    float mrun = -INFINITY;
    float l = 0.f;
    float acc[DHH] = {};

    for (int j = 0; j < WSZ; j++) {
        float s = 0.f;
#pragma unroll
        for (int d4 = 0; d4 < 8; d4++) {
            float4 kk = *(const float4*)(&ks[j][d4 * 4]);
            s += qr[d4*4+0]*kk.x + qr[d4*4+1]*kk.y + qr[d4*4+2]*kk.z + qr[d4*4+3]*kk.w;
        }
        s += pos[j * WSZ + i];
        if (s > mrun) {
            float c = __expf(mrun - s);
            mrun = s;
            l *= c;
#pragma unroll
            for (int d = 0; d < DHH; d++) acc[d] *= c;
        }
        float p = __expf(s - mrun);
        l += p;
#pragma unroll
        for (int d4 = 0; d4 < 8; d4++) {
            float4 vv = *(const float4*)(&vs[j][d4 * 4]);
            acc[d4*4+0] += p * vv.x;
            acc[d4*4+1] += p * vv.y;
            acc[d4*4+2] += p * vv.z;
            acc[d4*4+3] += p * vv.w;
        }
    }
    float inv = 1.f / l;
    size_t obase = (((size_t)(b * NWIN + n) * WSZ) + i) * CDIM + hh * DHH;
#pragma unroll
    for (int d = 0; d < DHH; d += 4) {
        __nv_bfloat16 h4[4];
        __nv_bfloat16 l4[4];
        split1(acc[d + 0] * inv, h4[0], l4[0]);
        split1(acc[d + 1] * inv, h4[1], l4[1]);
        split1(acc[d + 2] * inv, h4[2], l4[2]);
        split1(acc[d + 3] * inv, h4[3], l4[3]);
        *(uint2*)(g_ahi + obase + d) = *(uint2*)h4;
        *(uint2*)(g_alo + obase + d) = *(uint2*)l4;
    }
}

// ---------------- attention branch 2 (cross-window, seq=256) ----------------
__global__ __launch_bounds__(256) void attn2_kernel() {
    int m  = blockIdx.x;
    int hh = blockIdx.y;
    int b  = blockIdx.z;
    int i  = threadIdx.x;

    __shared__ float ks[128][36];
    __shared__ float vs[128][36];

    int h = ((i >> 4) << 3) + (m >> 3);
    int w = ((i & 15) << 3) + (m & 7);
    size_t grow = ((size_t)b << 14) + (h << 7) + w;

    float qr[DHH];
    {
        const float4* qp = (const float4*)(g_q + grow * 256 + 128 + hh * DHH);
#pragma unroll
        for (int d4 = 0; d4 < 8; d4++) {
            float4 q4 = qp[d4];
            qr[d4*4+0] = q4.x * QSCALE;
            qr[d4*4+1] = q4.y * QSCALE;
            qr[d4*4+2] = q4.z * QSCALE;
            qr[d4*4+3] = q4.w * QSCALE;
        }
    }

    const float* pos = g_pos2t + hh * NWIN * NWIN;
    float mrun = -INFINITY;
    float l = 0.f;
    float acc[DHH] = {};

    for (int jc = 0; jc < NWIN; jc += 128) {
        __syncthreads();
        {
            int t = threadIdx.x;
            int r = t & 127;
            int jw = jc + r;
            int hK = ((jw >> 4) << 3) + (m >> 3);
            int wK = ((jw & 15) << 3) + (m & 7);
            size_t gk = ((size_t)b << 14) + (hK << 7) + wK;
            if (t < 128) {
                const float4* kp = (const float4*)(g_kv + gk * 512 + 128 + hh * DHH);
#pragma unroll
                for (int d4 = 0; d4 < 8; d4++) *(float4*)(&ks[r][d4 * 4]) = kp[d4];
            } else {
                const float4* vp = (const float4*)(g_kv + gk * 512 + 384 + hh * DHH);
#pragma unroll
                for (int d4 = 0; d4 < 8; d4++) *(float4*)(&vs[r][d4 * 4]) = vp[d4];
            }
        }
        __syncthreads();

        for (int jj = 0; jj < 128; jj++) {
            int j = jc + jj;
            float s = 0.f;
#pragma unroll
            for (int d4 = 0; d4 < 8; d4++) {
                float4 kk = *(const float4*)(&ks[jj][d4 * 4]);
                s += qr[d4*4+0]*kk.x + qr[d4*4+1]*kk.y + qr[d4*4+2]*kk.z + qr[d4*4+3]*kk.w;
            }
            s += pos[j * NWIN + i];
            if (s > mrun) {
                float c = __expf(mrun - s);
                mrun = s;
                l *= c;
#pragma unroll
                for (int d = 0; d < DHH; d++) acc[d] *= c;
            }
            float p = __expf(s - mrun);
            l += p;
#pragma unroll
            for (int d4 = 0; d4 < 8; d4++) {
                float4 vv = *(const float4*)(&vs[jj][d4 * 4]);
                acc[d4*4+0] += p * vv.x;
                acc[d4*4+1] += p * vv.y;
                acc[d4*4+2] += p * vv.z;
                acc[d4*4+3] += p * vv.w;
            }
        }
    }
    float inv = 1.f / l;
    size_t obase = (((size_t)(b * NWIN + i) * WSZ) + m) * CDIM + 128 + hh * DHH;
#pragma unroll
    for (int d = 0; d < DHH; d += 4) {
        __nv_bfloat16 h4[4];
        __nv_bfloat16 l4[4];
        split1(acc[d + 0] * inv, h4[0], l4[0]);
        split1(acc[d + 1] * inv, h4[1], l4[1]);
        split1(acc[d + 2] * inv, h4[2], l4[2]);
        split1(acc[d + 3] * inv, h4[3], l4[3]);
        *(uint2*)(g_ahi + obase + d) = *(uint2*)h4;
        *(uint2*)(g_alo + obase + d) = *(uint2*)l4;
    }
}

// ---------------------------------------------------------------------------
extern "C" void kernel_launch(void* const* d_in, const int* in_sizes, int n_in,
                              void* d_out, int out_size) {
    const float* x   = (const float*)d_in[0];
    const float* Wq  = (const float*)d_in[1];
    const float* Wkv = (const float*)d_in[2];
    const float* Wo  = (const float*)d_in[3];
    const float* bo  = (const float*)d_in[4];
    const float* p1  = (const float*)d_in[5];
    const float* p2  = (const float*)d_in[6];
    float* out = (float*)d_out;

    pos_transpose<<<256, 256>>>(p1, p2);
    split_x<<<2048, 256>>>(x);
    split_wo<<<(CDIM * CDIM + 255) / 256, 256>>>(Wo);
    build_w<<<(CDIM * NQKV + 255) / 256, 256>>>(Wq, Wkv);

    gemm_wmma<<<dim3(6, 512), 256>>>(0, (float*)0, (const float*)0);
    attn1_kernel<<<dim3(256, 4, 4), 64>>>();
    attn2_kernel<<<dim3(64, 4, 4), 256>>>();
    gemm_wmma<<<dim3(2, 512), 256>>>(1, out, bo);
}

// round 5
// speedup vs baseline: 1.4914x; 1.0990x over previous
#include <cuda_runtime.h>
#include <cuda_bf16.h>
#include <mma.h>
#include <math.h>

using namespace nvcuda;

#define NB    4
#define SS    128
#define CDIM  256
#define NHH   4
#define DHH   32
#define NWIN  256
#define WSZ   64
#define MTOT  (NB*SS*SS)
#define NQKV  768
#define QSCALE 0.17677669529663687f

typedef unsigned long long ull;

// ---------------- scratch ----------------
__device__ float g_q  [MTOT * CDIM];
__device__ float g_kv [MTOT * 2 * CDIM];
__device__ __nv_bfloat16 g_xhi[MTOT * CDIM];
__device__ __nv_bfloat16 g_xlo[MTOT * CDIM];
__device__ __nv_bfloat16 g_ahi[MTOT * CDIM];
__device__ __nv_bfloat16 g_alo[MTOT * CDIM];
__device__ __nv_bfloat16 g_whi[CDIM * NQKV];
__device__ __nv_bfloat16 g_wlo[CDIM * NQKV];
__device__ __nv_bfloat16 g_wohi[CDIM * CDIM];
__device__ __nv_bfloat16 g_wolo[CDIM * CDIM];
__device__ float g_pos1t[NHH * WSZ * WSZ];
__device__ float g_pos2t[NHH * NWIN * NWIN];

// ---------------- helpers (no braces inside asm strings) ----------------
union F2U {
    float2 f;
    ull u;
};
__device__ __forceinline__ ull f2pack(float x, float y) {
    F2U t; t.f = make_float2(x, y); return t.u;
}
__device__ __forceinline__ float2 f2unpack(ull v) {
    F2U t; t.u = v; return t.f;
}
__device__ __forceinline__ ull ffma2(ull a, ull b, ull c) {
    ull d;
    asm("fma.rn.f32x2 %0,%1,%2,%3;" : "=l"(d) : "l"(a), "l"(b), "l"(c));
    return d;
}
__device__ __forceinline__ ull fmul2(ull a, ull b) {
    ull d;
    asm("mul.rn.f32x2 %0,%1,%2;" : "=l"(d) : "l"(a), "l"(b));
    return d;
}
__device__ __forceinline__ void split1(float x, __nv_bfloat16& h, __nv_bfloat16& l) {
    h = __float2bfloat16(x);
    l = __float2bfloat16(x - __bfloat162float(h));
}

// ---------------- pos transpose ----------------
__global__ void pos_transpose(const float* __restrict__ p1,
                              const float* __restrict__ p2) {
    int idx = blockIdx.x * blockDim.x + threadIdx.x;
    int stride = gridDim.x * blockDim.x;
    for (int i = idx; i < NHH * WSZ * WSZ; i += stride) {
        int hh = i / (WSZ * WSZ);
        int rem = i - hh * WSZ * WSZ;
        int r = rem / WSZ;
        int c = rem % WSZ;
        g_pos1t[(hh * WSZ + c) * WSZ + r] = p1[i];
    }
    for (int i = idx; i < NHH * NWIN * NWIN; i += stride) {
        int hh = i / (NWIN * NWIN);
        int rem = i - hh * NWIN * NWIN;
        int r = rem / NWIN;
        int c = rem % NWIN;
        g_pos2t[(hh * NWIN + c) * NWIN + r] = p2[i];
    }
}

// ---------------- conversions ----------------
__global__ void split_x(const float* __restrict__ src) {
    int idx = blockIdx.x * blockDim.x + threadIdx.x;
    int stride = gridDim.x * blockDim.x;
    const int n4 = MTOT * CDIM / 4;
    for (int i = idx; i < n4; i += stride) {
        float4 v = ((const float4*)src)[i];
        __nv_bfloat16 h4[4];
        __nv_bfloat16 l4[4];
        split1(v.x, h4[0], l4[0]);
        split1(v.y, h4[1], l4[1]);
        split1(v.z, h4[2], l4[2]);
        split1(v.w, h4[3], l4[3]);
        ((uint2*)g_xhi)[i] = *(uint2*)h4;
        ((uint2*)g_xlo)[i] = *(uint2*)l4;
    }
}

__global__ void split_wo(const float* __restrict__ Wo) {
    int i = blockIdx.x * blockDim.x + threadIdx.x;
    if (i < CDIM * CDIM) {
        split1(Wo[i], g_wohi[i], g_wolo[i]);
    }
}

__global__ void build_w(const float* __restrict__ Wq, const float* __restrict__ Wkv) {
    int idx = blockIdx.x * blockDim.x + threadIdx.x;
    if (idx < CDIM * NQKV) {
        int k = idx / NQKV;
        int c = idx % NQKV;
        float v = (c < 256) ? Wq[k * 256 + c] : Wkv[k * 512 + (c - 256)];
        split1(v, g_whi[idx], g_wlo[idx]);
    }
}

// ---------------- WMMA split-bf16 GEMM ----------------
__device__ __forceinline__ int remap_row(int row) {
    int b = row >> 14;
    int n = (row >> 6) & 255;
    int m = row & 63;
    int h = ((n >> 4) << 3) + (m >> 3);
    int w = ((n & 15) << 3) + (m & 7);
    return (b << 14) + (h << 7) + w;
}

__global__ __launch_bounds__(256) void gemm_wmma(
    int mode, float* __restrict__ outp, const float* __restrict__ bo)
{
    const int Ntot = mode ? 256 : NQKV;
    const __nv_bfloat16* __restrict__ Ahi = mode ? g_ahi : g_xhi;
    const __nv_bfloat16* __restrict__ Alo = mode ? g_alo : g_xlo;
    const __nv_bfloat16* __restrict__ Bhi = mode ? g_wohi : g_whi;
    const __nv_bfloat16* __restrict__ Blo = mode ? g_wolo : g_wlo;

    __shared__ __align__(32) __nv_bfloat16 As[2][128][40];
    __shared__ __align__(32) __nv_bfloat16 Bs[2][32][136];
    __shared__ __align__(32) float stg[8][16][16];

    const int tid = threadIdx.x;
    const int wid = tid >> 5;
    const int lane = tid & 31;
    const int nb0 = blockIdx.x * 128;
    const int mrow0 = blockIdx.y * 128;
    const int m0w = (wid & 3) * 32;
    const int n0w = (wid >> 2) * 64;

    wmma::fragment<wmma::accumulator, 16, 16, 16, float> cfrag[2][4];
#pragma unroll
    for (int mi = 0; mi < 2; mi++) {
#pragma unroll
        for (int ni = 0; ni < 4; ni++) {
            wmma::fill_fragment(cfrag[mi][ni], 0.0f);
        }
    }

    const int arow = tid >> 1;
    const int acol = (tid & 1) * 16;
    const int bkr = tid >> 4;
    const int bnc = (tid & 15) * 8;

    for (int k0 = 0; k0 < 256; k0 += 32) {
        __syncthreads();
        {
            const __nv_bfloat16* ah = Ahi + (size_t)(mrow0 + arow) * 256 + k0 + acol;
            const __nv_bfloat16* al = Alo + (size_t)(mrow0 + arow) * 256 + k0 + acol;
            *(uint4*)(&As[0][arow][acol])     = *(const uint4*)(ah);
            *(uint4*)(&As[0][arow][acol + 8]) = *(const uint4*)(ah + 8);
            *(uint4*)(&As[1][arow][acol])     = *(const uint4*)(al);
            *(uint4*)(&As[1][arow][acol + 8]) = *(const uint4*)(al + 8);
        }
#pragma unroll
        for (int p = 0; p < 32; p += 16) {
            *(uint4*)(&Bs[0][bkr + p][bnc]) =
                *(const uint4*)(Bhi + (size_t)(k0 + bkr + p) * Ntot + nb0 + bnc);
            *(uint4*)(&Bs[1][bkr + p][bnc]) =
                *(const uint4*)(Blo + (size_t)(k0 + bkr + p) * Ntot + nb0 + bnc);
        }
        __syncthreads();

#pragma unroll
        for (int ks = 0; ks < 32; ks += 16) {
            wmma::fragment<wmma::matrix_a, 16, 16, 16, __nv_bfloat16, wmma::row_major> afh[2];
            wmma::fragment<wmma::matrix_a, 16, 16, 16, __nv_bfloat16, wmma::row_major> afl[2];
            wmma::load_matrix_sync(afh[0], &As[0][m0w][ks], 40);
            wmma::load_matrix_sync(afh[1], &As[0][m0w + 16][ks], 40);
            wmma::load_matrix_sync(afl[0], &As[1][m0w][ks], 40);
            wmma::load_matrix_sync(afl[1], &As[1][m0w + 16][ks], 40);
#pragma unroll
            for (int ni = 0; ni < 4; ni++) {
                wmma::fragment<wmma::matrix_b, 16, 16, 16, __nv_bfloat16, wmma::row_major> bfh;
                wmma::fragment<wmma::matrix_b, 16, 16, 16, __nv_bfloat16, wmma::row_major> bfl;
                wmma::load_matrix_sync(bfh, &Bs[0][ks][n0w + ni * 16], 136);
                wmma::load_matrix_sync(bfl, &Bs[1][ks][n0w + ni * 16], 136);
#pragma unroll
                for (int mi = 0; mi < 2; mi++) {
                    wmma::mma_sync(cfrag[mi][ni], afh[mi], bfh, cfrag[mi][ni]);
                    wmma::mma_sync(cfrag[mi][ni], afh[mi], bfl, cfrag[mi][ni]);
                    wmma::mma_sync(cfrag[mi][ni], afl[mi], bfh, cfrag[mi][ni]);
                }
            }
        }
    }

    if (mode == 0) {
#pragma unroll
        for (int mi = 0; mi < 2; mi++) {
#pragma unroll
            for (int ni = 0; ni < 4; ni++) {
                int row = mrow0 + m0w + mi * 16;
                int col = nb0 + n0w + ni * 16;
                if (col < 256) {
                    wmma::store_matrix_sync(g_q + (size_t)row * 256 + col,
                                            cfrag[mi][ni], 256, wmma::mem_row_major);
                } else {
                    wmma::store_matrix_sync(g_kv + (size_t)row * 512 + (col - 256),
                                            cfrag[mi][ni], 512, wmma::mem_row_major);
                }
            }
        }
    } else {
#pragma unroll
        for (int mi = 0; mi < 2; mi++) {
#pragma unroll
            for (int ni = 0; ni < 4; ni++) {
                wmma::store_matrix_sync(&stg[wid][0][0], cfrag[mi][ni], 16, wmma::mem_row_major);
                __syncwarp();
                int row0 = mrow0 + m0w + mi * 16;
                int col0 = nb0 + n0w + ni * 16;
#pragma unroll
                for (int e = 0; e < 8; e++) {
                    int idx = lane * 8 + e;
                    int r = idx >> 4;
                    int c = idx & 15;
                    int grow = remap_row(row0 + r);
                    outp[(size_t)grow * 256 + col0 + c] = stg[wid][r][c] + bo[col0 + c];
                }
                __syncwarp();
            }
        }
    }
}

// ---------------- attention branch 1 (within-window, seq=64) ----------------
__global__ __launch_bounds__(64) void attn1_kernel() {
    int n  = blockIdx.x;
    int hh = blockIdx.y;
    int b  = blockIdx.z;
    int i  = threadIdx.x;

    __shared__ float ks[WSZ][36];
    __shared__ float vs[WSZ][36];

    int h = ((n >> 4) << 3) + (i >> 3);
    int w = ((n & 15) << 3) + (i & 7);
    size_t grow = ((size_t)b << 14) + (h << 7) + w;

    {
        const float4* kp = (const float4*)(g_kv + grow * 512 + hh * DHH);
        const float4* vp = (const float4*)(g_kv + grow * 512 + 256 + hh * DHH);
#pragma unroll
        for (int d4 = 0; d4 < 8; d4++) {
            *(float4*)(&ks[i][d4 * 4]) = kp[d4];
            *(float4*)(&vs[i][d4 * 4]) = vp[d4];
        }
    }
    ull qr2[16];
    {
        const float4* qp = (const float4*)(g_q + grow * 256 + hh * DHH);
#pragma unroll
        for (int d4 = 0; d4 < 8; d4++) {
            float4 q4 = qp[d4];
            qr2[2 * d4]     = f2pack(q4.x * QSCALE, q4.y * QSCALE);
            qr2[2 * d4 + 1] = f2pack(q4.z * QSCALE, q4.w * QSCALE);
        }
    }
    __syncthreads();

    const float* pos = g_pos1t + hh * WSZ * WSZ;
    float mrun = -INFINITY;
    float l = 0.f;
    ull acc2[16];
#pragma unroll
    for (int t = 0; t < 16; t++) acc2[t] = 0ULL;

#pragma unroll 2
    for (int j = 0; j < WSZ; j++) {
        float pb = pos[j * WSZ + i];
        const ulonglong2* kp2 = (const ulonglong2*)(&ks[j][0]);
        ull s2 = 0ULL;
#pragma unroll
        for (int t = 0; t < 8; t++) {
            ulonglong2 kk = kp2[t];
            s2 = ffma2(qr2[2 * t], kk.x, s2);
            s2 = ffma2(qr2[2 * t + 1], kk.y, s2);
        }
        float2 sv = f2unpack(s2);
        float s = sv.x + sv.y + pb;
        if (s > mrun) {
            float c = __expf(mrun - s);
            mrun = s;
            l *= c;
            ull cc2 = f2pack(c, c);
#pragma unroll
            for (int t = 0; t < 16; t++) acc2[t] = fmul2(acc2[t], cc2);
        }
        float p = __expf(s - mrun);
        l += p;
        ull pp2 = f2pack(p, p);
        const ulonglong2* vp2 = (const ulonglong2*)(&vs[j][0]);
#pragma unroll
        for (int t = 0; t < 8; t++) {
            ulonglong2 vv = vp2[t];
            acc2[2 * t]     = ffma2(pp2, vv.x, acc2[2 * t]);
            acc2[2 * t + 1] = ffma2(pp2, vv.y, acc2[2 * t + 1]);
        }
    }
    float inv = 1.f / l;
    size_t obase = (((size_t)(b * NWIN + n) * WSZ) + i) * CDIM + hh * DHH;
#pragma unroll
    for (int t = 0; t < 8; t++) {
        float2 p0 = f2unpack(acc2[2 * t]);
        float2 p1 = f2unpack(acc2[2 * t + 1]);
        __nv_bfloat16 h4[4];
        __nv_bfloat16 l4[4];
        split1(p0.x * inv, h4[0], l4[0]);
        split1(p0.y * inv, h4[1], l4[1]);
        split1(p1.x * inv, h4[2], l4[2]);
        split1(p1.y * inv, h4[3], l4[3]);
        *(uint2*)(g_ahi + obase + t * 4) = *(uint2*)h4;
        *(uint2*)(g_alo + obase + t * 4) = *(uint2*)l4;
    }
}

// ---------------- attention branch 2 (cross-window, seq=256) ----------------
__global__ __launch_bounds__(256) void attn2_kernel() {
    int m  = blockIdx.x;
    int hh = blockIdx.y;
    int b  = blockIdx.z;
    int i  = threadIdx.x;

    __shared__ float ks[128][36];
    __shared__ float vs[128][36];

    int h = ((i >> 4) << 3) + (m >> 3);
    int w = ((i & 15) << 3) + (m & 7);
    size_t grow = ((size_t)b << 14) + (h << 7) + w;

    ull qr2[16];
    {
        const float4* qp = (const float4*)(g_q + grow * 256 + 128 + hh * DHH);
#pragma unroll
        for (int d4 = 0; d4 < 8; d4++) {
            float4 q4 = qp[d4];
            qr2[2 * d4]     = f2pack(q4.x * QSCALE, q4.y * QSCALE);
            qr2[2 * d4 + 1] = f2pack(q4.z * QSCALE, q4.w * QSCALE);
        }
    }

    const float* pos = g_pos2t + hh * NWIN * NWIN;
    float mrun = -INFINITY;
    float l = 0.f;
    ull acc2[16];
#pragma unroll
    for (int t = 0; t < 16; t++) acc2[t] = 0ULL;

    for (int jc = 0; jc < NWIN; jc += 128) {
        __syncthreads();
        {
            int t = threadIdx.x;
            int r = t & 127;
            int jw = jc + r;
            int hK = ((jw >> 4) << 3) + (m >> 3);
            int wK = ((jw & 15) << 3) + (m & 7);
            size_t gk = ((size_t)b << 14) + (hK << 7) + wK;
            if (t < 128) {
                const float4* kp = (const float4*)(g_kv + gk * 512 + 128 + hh * DHH);
#pragma unroll
                for (int d4 = 0; d4 < 8; d4++) *(float4*)(&ks[r][d4 * 4]) = kp[d4];
            } else {
                const float4* vp = (const float4*)(g_kv + gk * 512 + 384 + hh * DHH);
#pragma unroll
                for (int d4 = 0; d4 < 8; d4++) *(float4*)(&vs[r][d4 * 4]) = vp[d4];
            }
        }
        __syncthreads();

#pragma unroll 2
        for (int jj = 0; jj < 128; jj++) {
            float pb = pos[(jc + jj) * NWIN + i];
            const ulonglong2* kp2 = (const ulonglong2*)(&ks[jj][0]);
            ull s2 = 0ULL;
#pragma unroll
            for (int t = 0; t < 8; t++) {
                ulonglong2 kk = kp2[t];
                s2 = ffma2(qr2[2 * t], kk.x, s2);
                s2 = ffma2(qr2[2 * t + 1], kk.y, s2);
            }
            float2 sv = f2unpack(s2);
            float s = sv.x + sv.y + pb;
            if (s > mrun) {
                float c = __expf(mrun - s);
                mrun = s;
                l *= c;
                ull cc2 = f2pack(c, c);
#pragma unroll
                for (int t = 0; t < 16; t++) acc2[t] = fmul2(acc2[t], cc2);
            }
            float p = __expf(s - mrun);
            l += p;
            ull pp2 = f2pack(p, p);
            const ulonglong2* vp2 = (const ulonglong2*)(&vs[jj][0]);
#pragma unroll
            for (int t = 0; t < 8; t++) {
                ulonglong2 vv = vp2[t];
                acc2[2 * t]     = ffma2(pp2, vv.x, acc2[2 * t]);
                acc2[2 * t + 1] = ffma2(pp2, vv.y, acc2[2 * t + 1]);
            }
        }
    }
    float inv = 1.f / l;
    size_t obase = (((size_t)(b * NWIN + i) * WSZ) + m) * CDIM + 128 + hh * DHH;
#pragma unroll
    for (int t = 0; t < 8; t++) {
        float2 p0 = f2unpack(acc2[2 * t]);
        float2 p1 = f2unpack(acc2[2 * t + 1]);
        __nv_bfloat16 h4[4];
        __nv_bfloat16 l4[4];
        split1(p0.x * inv, h4[0], l4[0]);
        split1(p0.y * inv, h4[1], l4[1]);
        split1(p1.x * inv, h4[2], l4[2]);
        split1(p1.y * inv, h4[3], l4[3]);
        *(uint2*)(g_ahi + obase + t * 4) = *(uint2*)h4;
        *(uint2*)(g_alo + obase + t * 4) = *(uint2*)l4;
    }
}

// ---------------------------------------------------------------------------
extern "C" void kernel_launch(void* const* d_in, const int* in_sizes, int n_in,
                              void* d_out, int out_size) {
    const float* x   = (const float*)d_in[0];
    const float* Wq  = (const float*)d_in[1];
    const float* Wkv = (const float*)d_in[2];
    const float* Wo  = (const float*)d_in[3];
    const float* bo  = (const float*)d_in[4];
    const float* p1  = (const float*)d_in[5];
    const float* p2  = (const float*)d_in[6];
    float* out = (float*)d_out;

    pos_transpose<<<256, 256>>>(p1, p2);
    split_x<<<2048, 256>>>(x);
    split_wo<<<(CDIM * CDIM + 255) / 256, 256>>>(Wo);
    build_w<<<(CDIM * NQKV + 255) / 256, 256>>>(Wq, Wkv);

    gemm_wmma<<<dim3(6, 512), 256>>>(0, (float*)0, (const float*)0);
    attn1_kernel<<<dim3(256, 4, 4), 64>>>();
    attn2_kernel<<<dim3(64, 4, 4), 256>>>();
    gemm_wmma<<<dim3(2, 512), 256>>>(1, out, bo);
}